// round 6
// baseline (speedup 1.0000x reference)
#include <cuda_runtime.h>

#define T_DIM 512
#define SPB   256   // timesteps per block
#define TPB   128   // threads per block (2 timesteps each)
#define N_STEPS 5

__device__ __forceinline__ float sgnf(float x) {
    return (x > 0.0f) ? 1.0f : ((x < 0.0f) ? -1.0f : 0.0f);
}

__device__ __forceinline__ float rescale_f(float x) {
    const float EPS = 1e-3f;
    return sgnf(x) * (sqrtf(fabsf(x) + 1.0f) - 1.0f) + EPS * x;
}

__device__ __forceinline__ float inv_rescale_f(float x) {
    const float EPS = 1e-3f;
    float sqrt_arg = 1.0f + 4.0f * EPS * (fabsf(x) + 1.0f + EPS);
    float r = (sqrtf(sqrt_arg) - 1.0f) / (2.0f * EPS);
    return sgnf(x) * (r * r - 1.0f);
}

__global__ __launch_bounds__(TPB)
void nstep_qloss_kernel(const float* __restrict__ cq,
                        const float* __restrict__ nq,
                        const float* __restrict__ logp,
                        const float* __restrict__ rw,
                        const float* __restrict__ done,
                        const float* __restrict__ mask,
                        float* __restrict__ out)
{
    // A[t] = m*reward + gamma*inv_qw*(md*logp/3); z lane dead (stored 0)
    __shared__ float4 s_A[SPB + N_STEPS - 1];

    const float GAMMA  = 0.997f;
    const float GAMMA2 = 0.997f * 0.997f;
    const float GAMMA3 = GAMMA2 * 0.997f;
    const float GAMMA4 = GAMMA3 * 0.997f;
    const float GAMMA5 = GAMMA4 * 0.997f;
    const float LN_GAMMA = -0.003004509021390342f; // ln(0.997)

    const int b    = blockIdx.x;
    const int base = blockIdx.y * SPB;       // 0 or 256
    const int l    = threadIdx.x;
    const int lt0  = 2 * l;                  // local timestep of first element
    const int t0   = base + lt0;             // global timestep
    const int row  = b * T_DIM;              // float4-unit row base
    const int bt0  = row + t0;
    const int sc   = (row + t0) >> 1;        // float2-unit index for scalars

    // gathered indices (clamped at row end)
    const int idx0 = min(T_DIM - 1, t0 + 4);
    const int idx1 = min(T_DIM - 1, t0 + 5);

    // ---- hoisted global loads (max MLP) ----
    float4 c0 = ((const float4*)cq)[bt0];
    float4 c1 = ((const float4*)cq)[bt0 + 1];
    float2 m2 = ((const float2*)mask)[sc];
    float2 d2 = ((const float2*)done)[sc];
    float2 p2 = ((const float2*)logp)[sc];
    float4 r0 = ((const float4*)rw)[bt0];
    float4 r1 = ((const float4*)rw)[bt0 + 1];
    // shifted (gathered) streams, direct from global — no staging
    float  mi0 = mask[row + idx0];
    float  mi1 = mask[row + idx1];
    float  di0 = done[row + idx0];
    float  di1 = done[row + idx1];
    float4 n0  = ((const float4*)nq)[row + idx0];
    float4 n1  = ((const float4*)nq)[row + idx1];

    // halo: threads 0..3 build A for t = base+SPB+l (zero past row end)
    float hm = 0.f, hd = 0.f, hp = 0.f;
    float4 hr = make_float4(0.f, 0.f, 0.f, 0.f);
    const int th = base + SPB + l;
    if (l < N_STEPS - 1 && th < T_DIM) {
        hm = mask[row + th];
        hd = done[row + th];
        hp = logp[row + th];
        hr = ((const float4*)rw)[row + th];
    }

    const float md0 = m2.x * (1.0f - d2.x);
    const float md1 = m2.y * (1.0f - d2.y);
    const float lb0 = (GAMMA / 3.0f) * md0 * p2.x;   // per-lane *inv_qw = [1,2,-,0.5]
    const float lb1 = (GAMMA / 3.0f) * md1 * p2.y;

    float4 a0, a1;
    a0.x = fmaf(m2.x, r0.x, lb0);
    a0.y = fmaf(m2.x, r0.y, 2.0f * lb0);
    a0.z = 0.0f;
    a0.w = fmaf(m2.x, r0.w, 0.5f * lb0);
    a1.x = fmaf(m2.y, r1.x, lb1);
    a1.y = fmaf(m2.y, r1.y, 2.0f * lb1);
    a1.z = 0.0f;
    a1.w = fmaf(m2.y, r1.w, 0.5f * lb1);
    s_A[lt0]     = a0;
    s_A[lt0 + 1] = a1;
    if (l < N_STEPS - 1) {
        const float hmd = hm * (1.0f - hd);
        const float hlb = (GAMMA / 3.0f) * hmd * hp;
        float4 ha;
        ha.x = fmaf(hm, hr.x, hlb);
        ha.y = fmaf(hm, hr.y, 2.0f * hlb);
        ha.z = 0.0f;
        ha.w = fmaf(hm, hr.w, 0.5f * hlb);
        s_A[SPB + l] = ha;           // zero automatically when th >= T_DIM
    }

    // gathered next-q term in registers
    const float mdi0 = mi0 * (1.0f - di0);
    const float mdi1 = mi1 * (1.0f - di1);
    float v0x = mdi0 * inv_rescale_f(n0.x);
    float v0y = mdi0 * inv_rescale_f(n0.y);
    float v0w = mdi0 * inv_rescale_f(n0.w);
    float v1x = mdi1 * inv_rescale_f(n1.x);
    float v1y = mdi1 * inv_rescale_f(n1.y);
    float v1w = mdi1 * inv_rescale_f(n1.w);

    __syncthreads();

    float4 A2 = s_A[lt0 + 2];
    float4 A3 = s_A[lt0 + 3];
    float4 A4 = s_A[lt0 + 4];
    float4 A5 = s_A[lt0 + 5];

    // rs1 = sum_{n=0..4} gamma^n A[t0+1+n]
    float rs1x = fmaf(GAMMA4, A5.x, fmaf(GAMMA3, A4.x, fmaf(GAMMA2, A3.x, fmaf(GAMMA, A2.x, a1.x))));
    float rs1y = fmaf(GAMMA4, A5.y, fmaf(GAMMA3, A4.y, fmaf(GAMMA2, A3.y, fmaf(GAMMA, A2.y, a1.y))));
    float rs1w = fmaf(GAMMA4, A5.w, fmaf(GAMMA3, A4.w, fmaf(GAMMA2, A3.w, fmaf(GAMMA, A2.w, a1.w))));
    // rs0 = A[t0] + gamma*rs1 - gamma^5 * A[t0+5]
    float rs0x = fmaf(GAMMA, rs1x, fmaf(-GAMMA5, A5.x, a0.x));
    float rs0y = fmaf(GAMMA, rs1y, fmaf(-GAMMA5, A5.y, a0.y));
    float rs0w = fmaf(GAMMA, rs1w, fmaf(-GAMMA5, A5.w, a0.w));

    const float gi0 = expf((float)idx0 * LN_GAMMA);          // gamma^idx (absolute)
    const float gi1 = (idx1 == idx0) ? gi0 : gi0 * GAMMA;

    // Q_WEIGHTS = [1, 0.5, 0, 2]
    float e0x = c0.x - rescale_f(fmaf(gi0, v0x, rs0x));
    float e0y = c0.y - rescale_f(fmaf(gi0, v0y, rs0y));
    float e0w = c0.w - rescale_f(fmaf(gi0, v0w, rs0w));
    float e1x = c1.x - rescale_f(fmaf(gi1, v1x, rs1x));
    float e1y = c1.y - rescale_f(fmaf(gi1, v1y, rs1y));
    float e1w = c1.w - rescale_f(fmaf(gi1, v1w, rs1w));

    float4 o0, o1;
    o0.x = 0.5f  * m2.x * e0x * e0x;
    o0.y = 0.25f * m2.x * e0y * e0y;
    o0.z = 0.0f;
    o0.w = m2.x * e0w * e0w;
    o1.x = 0.5f  * m2.y * e1x * e1x;
    o1.y = 0.25f * m2.y * e1y * e1y;
    o1.z = 0.0f;
    o1.w = m2.y * e1w * e1w;

    ((float4*)out)[bt0]     = o0;
    ((float4*)out)[bt0 + 1] = o1;
}

extern "C" void kernel_launch(void* const* d_in, const int* in_sizes, int n_in,
                              void* d_out, int out_size)
{
    // metadata order: current_q_value, next_q_value, log_p, reward, is_done, mask
    const float* cq   = (const float*)d_in[0];
    const float* nq   = (const float*)d_in[1];
    const float* logp = (const float*)d_in[2];
    const float* rw   = (const float*)d_in[3];
    const float* done = (const float*)d_in[4];
    const float* mask = (const float*)d_in[5];
    float* out = (float*)d_out;

    int B = in_sizes[2] / T_DIM;   // log_p has B*T elements
    dim3 grid(B, T_DIM / SPB);
    nstep_qloss_kernel<<<grid, TPB>>>(cq, nq, logp, rw, done, mask, out);
}

// round 8
// speedup vs baseline: 1.0081x; 1.0081x over previous
#include <cuda_runtime.h>

#define T_DIM 512
#define TPB   256
#define N_STEPS 5

__device__ __forceinline__ float sgnf(float x) {
    return (x > 0.0f) ? 1.0f : ((x < 0.0f) ? -1.0f : 0.0f);
}

__device__ __forceinline__ float rescale_f(float x) {
    const float EPS = 1e-3f;
    return sgnf(x) * (sqrtf(fabsf(x) + 1.0f) - 1.0f) + EPS * x;
}

__device__ __forceinline__ float inv_rescale_f(float x) {
    const float EPS = 1e-3f;
    float sqrt_arg = 1.0f + 4.0f * EPS * (fabsf(x) + 1.0f + EPS);
    float r = (sqrtf(sqrt_arg) - 1.0f) / (2.0f * EPS);
    return sgnf(x) * (r * r - 1.0f);
}

__global__ __launch_bounds__(TPB)
void nstep_qloss_kernel(const float* __restrict__ cq,
                        const float* __restrict__ nq,
                        const float* __restrict__ logp,
                        const float* __restrict__ rw,
                        const float* __restrict__ done,
                        const float* __restrict__ mask,
                        float* __restrict__ out)
{
    // Only A is staged in shared: A[t] = m*reward + gamma*inv_qw*(md*logp/3)
    __shared__ float4 s_A[T_DIM + N_STEPS - 1];

    const float GAMMA  = 0.997f;
    const float GAMMA2 = 0.997f * 0.997f;
    const float GAMMA3 = GAMMA2 * 0.997f;
    const float GAMMA4 = GAMMA3 * 0.997f;
    const float GAMMA5 = GAMMA4 * 0.997f;
    const float LN_GAMMA = -0.003004509021390342f; // ln(0.997)

    const int b   = blockIdx.x;
    const int l   = threadIdx.x;
    const int t0  = 2 * l;
    const int row = b * T_DIM;
    const int bt0 = row + t0;              // float4-unit index for Q=4 streams
    const int sc  = b * TPB + l;           // float2-unit index for scalar streams

    // gathered indices (clamped at row end; last 2 threads broadcast-read 511)
    const int idx0 = min(T_DIM - 1, t0 + 4);
    const int idx1 = min(T_DIM - 1, t0 + 5);

    // ---- hoisted global loads (max MLP) ----
    float4 c0 = ((const float4*)cq)[bt0];
    float4 c1 = ((const float4*)cq)[bt0 + 1];
    float2 m2 = ((const float2*)mask)[sc];
    float2 d2 = ((const float2*)done)[sc];
    float2 p2 = ((const float2*)logp)[sc];
    float4 r0 = ((const float4*)rw)[bt0];
    float4 r1 = ((const float4*)rw)[bt0 + 1];
    // shifted (gathered) streams loaded directly from global — no staging
    float  mi0 = mask[row + idx0];
    float  mi1 = mask[row + idx1];
    float  di0 = done[row + idx0];
    float  di1 = done[row + idx1];
    float4 n0  = ((const float4*)nq)[row + idx0];
    float4 n1  = ((const float4*)nq)[row + idx1];

    const float md0 = m2.x * (1.0f - d2.x);
    const float md1 = m2.y * (1.0f - d2.y);
    const float lb0 = (GAMMA / 3.0f) * md0 * p2.x;   // per-lane *inv_qw = [1,2,-,0.5]
    const float lb1 = (GAMMA / 3.0f) * md1 * p2.y;

    float4 a0, a1;
    a0.x = fmaf(m2.x, r0.x, lb0);
    a0.y = fmaf(m2.x, r0.y, 2.0f * lb0);
    a0.z = 0.0f;
    a0.w = fmaf(m2.x, r0.w, 0.5f * lb0);
    a1.x = fmaf(m2.y, r1.x, lb1);
    a1.y = fmaf(m2.y, r1.y, 2.0f * lb1);
    a1.z = 0.0f;
    a1.w = fmaf(m2.y, r1.w, 0.5f * lb1);
    s_A[t0]     = a0;
    s_A[t0 + 1] = a1;
    if (l < 2) {
        s_A[T_DIM + 2 * l]     = make_float4(0.f, 0.f, 0.f, 0.f);
        s_A[T_DIM + 2 * l + 1] = make_float4(0.f, 0.f, 0.f, 0.f);
    }

    // gathered next-q term computed directly in registers
    const float mdi0 = mi0 * (1.0f - di0);
    const float mdi1 = mi1 * (1.0f - di1);
    float v0x = mdi0 * inv_rescale_f(n0.x);
    float v0y = mdi0 * inv_rescale_f(n0.y);
    float v0w = mdi0 * inv_rescale_f(n0.w);
    float v1x = mdi1 * inv_rescale_f(n1.x);
    float v1y = mdi1 * inv_rescale_f(n1.y);
    float v1w = mdi1 * inv_rescale_f(n1.w);

    __syncthreads();

    // window values A[t0+2 .. t0+5] from shared; A[t0], A[t0+1] in regs
    float4 A2 = s_A[t0 + 2];
    float4 A3 = s_A[t0 + 3];
    float4 A4 = s_A[t0 + 4];
    float4 A5 = s_A[t0 + 5];

    // rs1 = sum_{n=0..4} gamma^n A[t0+1+n]
    float rs1x = fmaf(GAMMA4, A5.x, fmaf(GAMMA3, A4.x, fmaf(GAMMA2, A3.x, fmaf(GAMMA, A2.x, a1.x))));
    float rs1y = fmaf(GAMMA4, A5.y, fmaf(GAMMA3, A4.y, fmaf(GAMMA2, A3.y, fmaf(GAMMA, A2.y, a1.y))));
    float rs1w = fmaf(GAMMA4, A5.w, fmaf(GAMMA3, A4.w, fmaf(GAMMA2, A3.w, fmaf(GAMMA, A2.w, a1.w))));
    // rs0 = A[t0] + gamma*rs1 - gamma^5 * A[t0+5]
    float rs0x = fmaf(GAMMA, rs1x, fmaf(-GAMMA5, A5.x, a0.x));
    float rs0y = fmaf(GAMMA, rs1y, fmaf(-GAMMA5, A5.y, a0.y));
    float rs0w = fmaf(GAMMA, rs1w, fmaf(-GAMMA5, A5.w, a0.w));

    const float gi0 = expf((float)idx0 * LN_GAMMA);          // gamma^idx (absolute)
    const float gi1 = (idx1 == idx0) ? gi0 : gi0 * GAMMA;

    // Q_WEIGHTS = [1, 0.5, 0, 2]
    float e0x = c0.x - rescale_f(fmaf(gi0, v0x, rs0x));
    float e0y = c0.y - rescale_f(fmaf(gi0, v0y, rs0y));
    float e0w = c0.w - rescale_f(fmaf(gi0, v0w, rs0w));
    float e1x = c1.x - rescale_f(fmaf(gi1, v1x, rs1x));
    float e1y = c1.y - rescale_f(fmaf(gi1, v1y, rs1y));
    float e1w = c1.w - rescale_f(fmaf(gi1, v1w, rs1w));

    float4 o0, o1;
    o0.x = 0.5f  * m2.x * e0x * e0x;
    o0.y = 0.25f * m2.x * e0y * e0y;
    o0.z = 0.0f;
    o0.w = m2.x * e0w * e0w;
    o1.x = 0.5f  * m2.y * e1x * e1x;
    o1.y = 0.25f * m2.y * e1y * e1y;
    o1.z = 0.0f;
    o1.w = m2.y * e1w * e1w;

    ((float4*)out)[bt0]     = o0;
    ((float4*)out)[bt0 + 1] = o1;
}

extern "C" void kernel_launch(void* const* d_in, const int* in_sizes, int n_in,
                              void* d_out, int out_size)
{
    // metadata order: current_q_value, next_q_value, log_p, reward, is_done, mask
    const float* cq   = (const float*)d_in[0];
    const float* nq   = (const float*)d_in[1];
    const float* logp = (const float*)d_in[2];
    const float* rw   = (const float*)d_in[3];
    const float* done = (const float*)d_in[4];
    const float* mask = (const float*)d_in[5];
    float* out = (float*)d_out;

    int B = in_sizes[2] / T_DIM;   // log_p has B*T elements

    // Occupancy cap via unused dynamic smem.
    // static s_A = 8256 B; dynamic 40704 B -> total 48960 B <= 49152 B
    // (default per-block limit, no cudaFuncSetAttribute needed).
    // ~49KB/CTA -> 4 CTAs/SM -> n_conc = 592 -> 4096/592 = 6.92 waves
    // (tail waste ~1.2% vs 7.7% at 5 CTAs/SM).
    nstep_qloss_kernel<<<B, TPB, 40704>>>(cq, nq, logp, rw, done, mask, out);
}